// round 1
// baseline (speedup 1.0000x reference)
#include <cuda_runtime.h>
#include <cuda_bf16.h>

#define D_MODELX 1024
#define NUM_HEADSX 16
#define D_HEADX 64
#define BATCHX 4
#define SEQX 2048
#define M_TOK (BATCHX * SEQX)   // 8192

// ---- static device scratch (no allocations allowed) ----
__device__ float g_Q[(size_t)M_TOK * D_MODELX];
__device__ float g_K[(size_t)M_TOK * D_MODELX];
__device__ float g_V[(size_t)M_TOK * D_MODELX];
__device__ float g_O[(size_t)M_TOK * D_MODELX];
__device__ float g_P[(size_t)BATCHX * NUM_HEADSX * SEQX * SEQX];  // 1 GiB

// ============================================================================
// Generic tiled SGEMM: C = alpha * A @ op(B) + bias
//   BT=true : B is [N,K] row-major (C[m,n] = sum_k A[m,k] * B[n,k])  "NT"
//   BT=false: B is [K,N] row-major (C[m,n] = sum_k A[m,k] * B[k,n])  "NN"
// MODE 0: plain (z unused, grid.z==1)
// MODE 1: scores  — z = b*16+h; A=Q head slice, B=K head slice, C=P[z]
// MODE 2: AV      — z = b*16+h; A=P[z], B=V head slice, C=O head slice
// Block: 64x64 tile, BK=16, 256 threads, 4x4 micro-tile. All dims divide.
// ============================================================================
template <bool BT, int MODE>
__global__ __launch_bounds__(256)
void gemm_kernel(const float* __restrict__ A,
                 const float* __restrict__ B,
                 float* __restrict__ C,
                 int lda, int ldb, int ldc,
                 int K, float alpha,
                 const float* __restrict__ bias)
{
    __shared__ float As[16][68];
    __shared__ float Bs[16][68];

    if (MODE == 1) {
        int z = blockIdx.z;
        int b = z >> 4, h = z & 15;
        A += (long long)b * SEQX * D_MODELX + h * D_HEADX;
        B += (long long)b * SEQX * D_MODELX + h * D_HEADX;
        C += (long long)z * SEQX * SEQX;
    } else if (MODE == 2) {
        int z = blockIdx.z;
        int b = z >> 4, h = z & 15;
        A += (long long)z * SEQX * SEQX;
        B += (long long)b * SEQX * D_MODELX + h * D_HEADX;
        C += (long long)b * SEQX * D_MODELX + h * D_HEADX;
    }

    const int m0 = blockIdx.y * 64;
    const int n0 = blockIdx.x * 64;
    const int t  = threadIdx.x;      // 0..255
    const int tx = t & 15;           // N direction
    const int ty = t >> 4;           // M direction

    float acc[4][4];
    #pragma unroll
    for (int i = 0; i < 4; i++)
        #pragma unroll
        for (int j = 0; j < 4; j++) acc[i][j] = 0.0f;

    for (int k0 = 0; k0 < K; k0 += 16) {
        // --- load A tile -> As[k][m] (A is [M,K] row-major, k contiguous)
        #pragma unroll
        for (int i = 0; i < 4; i++) {
            int idx = t + i * 256;
            int m = idx >> 4, k = idx & 15;
            As[k][m] = A[(long long)(m0 + m) * lda + (k0 + k)];
        }
        // --- load B tile -> Bs[k][n]
        if (BT) {
            #pragma unroll
            for (int i = 0; i < 4; i++) {
                int idx = t + i * 256;
                int n = idx >> 4, k = idx & 15;
                Bs[k][n] = B[(long long)(n0 + n) * ldb + (k0 + k)];
            }
        } else {
            #pragma unroll
            for (int i = 0; i < 4; i++) {
                int idx = t + i * 256;
                int k = idx >> 6, n = idx & 63;
                Bs[k][n] = B[(long long)(k0 + k) * ldb + (n0 + n)];
            }
        }
        __syncthreads();

        #pragma unroll
        for (int kk = 0; kk < 16; kk++) {
            float4 av = *(const float4*)&As[kk][ty * 4];
            float4 bv = *(const float4*)&Bs[kk][tx * 4];
            float a[4] = {av.x, av.y, av.z, av.w};
            float b4[4] = {bv.x, bv.y, bv.z, bv.w};
            #pragma unroll
            for (int i = 0; i < 4; i++)
                #pragma unroll
                for (int j = 0; j < 4; j++)
                    acc[i][j] = fmaf(a[i], b4[j], acc[i][j]);
        }
        __syncthreads();
    }

    // --- epilogue
    float4 bb = make_float4(0.f, 0.f, 0.f, 0.f);
    if (bias) bb = *(const float4*)&bias[n0 + tx * 4];
    #pragma unroll
    for (int i = 0; i < 4; i++) {
        float4 r;
        r.x = acc[i][0] * alpha + bb.x;
        r.y = acc[i][1] * alpha + bb.y;
        r.z = acc[i][2] * alpha + bb.z;
        r.w = acc[i][3] * alpha + bb.w;
        *(float4*)&C[(long long)(m0 + ty * 4 + i) * ldc + n0 + tx * 4] = r;
    }
}

// ============================================================================
// Row softmax over P, in place. One block per row (B*H*S rows of length SEQ).
// ============================================================================
__global__ __launch_bounds__(256)
void softmax_kernel(float* __restrict__ P)
{
    __shared__ float red[8];
    long long row = blockIdx.x;
    float* p = P + row * SEQX;
    int t = threadIdx.x;

    float vals[8];
    float mx = -1e30f;
    #pragma unroll
    for (int i = 0; i < 8; i++) {
        vals[i] = p[t + i * 256];
        mx = fmaxf(mx, vals[i]);
    }
    #pragma unroll
    for (int o = 16; o > 0; o >>= 1)
        mx = fmaxf(mx, __shfl_xor_sync(0xffffffffu, mx, o));
    if ((t & 31) == 0) red[t >> 5] = mx;
    __syncthreads();
    float bmx = red[0];
    #pragma unroll
    for (int w = 1; w < 8; w++) bmx = fmaxf(bmx, red[w]);

    float s = 0.f;
    #pragma unroll
    for (int i = 0; i < 8; i++) {
        vals[i] = __expf(vals[i] - bmx);
        s += vals[i];
    }
    #pragma unroll
    for (int o = 16; o > 0; o >>= 1)
        s += __shfl_xor_sync(0xffffffffu, s, o);
    __syncthreads();                 // protect red reuse
    if ((t & 31) == 0) red[t >> 5] = s;
    __syncthreads();
    float bs = 0.f;
    #pragma unroll
    for (int w = 0; w < 8; w++) bs += red[w];

    float inv = 1.0f / bs;
    #pragma unroll
    for (int i = 0; i < 8; i++)
        p[t + i * 256] = vals[i] * inv;
}

// ============================================================================
// avg[b,q,k] = (1/H) * sum_h P[b,h,q,k]
// ============================================================================
__global__ __launch_bounds__(256)
void avg_kernel(const float* __restrict__ P, float* __restrict__ avg)
{
    long long i = (long long)blockIdx.x * 256 + threadIdx.x;  // over B*S*S
    long long b  = i / ((long long)SEQX * SEQX);
    long long qk = i - b * (long long)SEQX * SEQX;
    const float* base = P + b * NUM_HEADSX * (long long)SEQX * SEQX + qk;
    float s = 0.f;
    #pragma unroll
    for (int h = 0; h < NUM_HEADSX; h++)
        s += base[(long long)h * SEQX * SEQX];
    avg[i] = s * (1.0f / NUM_HEADSX);
}

// ============================================================================
// launch
// ============================================================================
extern "C" void kernel_launch(void* const* d_in, const int* in_sizes, int n_in,
                              void* d_out, int out_size)
{
    const float* x_q = (const float*)d_in[0];
    const float* x_k = (const float*)d_in[1];
    const float* x_v = (const float*)d_in[2];
    const float* Wq  = (const float*)d_in[3];
    const float* bq  = (const float*)d_in[4];
    const float* Wk  = (const float*)d_in[5];
    const float* bk  = (const float*)d_in[6];
    const float* Wv  = (const float*)d_in[7];
    const float* bv  = (const float*)d_in[8];
    const float* Wo  = (const float*)d_in[9];
    const float* bo  = (const float*)d_in[10];

    float* out = (float*)d_out;
    float* avg = out + (long long)M_TOK * D_MODELX;

    float *gQ, *gK, *gV, *gO, *gP;
    cudaGetSymbolAddress((void**)&gQ, g_Q);
    cudaGetSymbolAddress((void**)&gK, g_K);
    cudaGetSymbolAddress((void**)&gV, g_V);
    cudaGetSymbolAddress((void**)&gO, g_O);
    cudaGetSymbolAddress((void**)&gP, g_P);

    dim3 blk(256);

    // 1-3) input projections: [8192,1024] @ W^T + b
    dim3 gproj(D_MODELX / 64, M_TOK / 64, 1);   // (16, 128)
    gemm_kernel<true, 0><<<gproj, blk>>>(x_q, Wq, gQ, D_MODELX, D_MODELX, D_MODELX,
                                         D_MODELX, 1.0f, bq);
    gemm_kernel<true, 0><<<gproj, blk>>>(x_k, Wk, gK, D_MODELX, D_MODELX, D_MODELX,
                                         D_MODELX, 1.0f, bk);
    gemm_kernel<true, 0><<<gproj, blk>>>(x_v, Wv, gV, D_MODELX, D_MODELX, D_MODELX,
                                         D_MODELX, 1.0f, bv);

    // 4) scores: P[z] = (Q_h @ K_h^T) / 8, per (b,h)
    dim3 gsc(SEQX / 64, SEQX / 64, BATCHX * NUM_HEADSX);  // (32, 32, 64)
    gemm_kernel<true, 1><<<gsc, blk>>>(gQ, gK, gP, D_MODELX, D_MODELX, SEQX,
                                       D_HEADX, 0.125f, nullptr);

    // 5) softmax rows in place
    softmax_kernel<<<(unsigned)((long long)BATCHX * NUM_HEADSX * SEQX), blk>>>(gP);

    // 6) head-average attention -> second half of d_out
    avg_kernel<<<(unsigned)(((long long)BATCHX * SEQX * SEQX) / 256), blk>>>(gP, avg);

    // 7) AV: O_h = P[z] @ V_h  (NN gemm, N = 64)
    dim3 gav(D_HEADX / 64, SEQX / 64, BATCHX * NUM_HEADSX);  // (1, 32, 64)
    gemm_kernel<false, 2><<<gav, blk>>>(gP, gV, gO, SEQX, D_MODELX, D_MODELX,
                                        SEQX, 1.0f, nullptr);

    // 8) output projection -> first half of d_out
    gemm_kernel<true, 0><<<gproj, blk>>>(gO, Wo, out, D_MODELX, D_MODELX, D_MODELX,
                                         D_MODELX, 1.0f, bo);
}

// round 2
// speedup vs baseline: 2.3025x; 2.3025x over previous
#include <cuda_runtime.h>
#include <cuda_bf16.h>
#include <cstdint>

#define D_MODELX 1024
#define NUM_HEADSX 16
#define D_HEADX 64
#define BATCHX 4
#define SEQX 2048
#define M_TOK (BATCHX * SEQX)   // 8192

// ---- static device scratch ----
__device__ float g_Q[(size_t)M_TOK * D_MODELX];
__device__ float g_K[(size_t)M_TOK * D_MODELX];
__device__ float g_Vt[(size_t)M_TOK * D_MODELX];  // [B*H][Dh][S] transposed V
__device__ float g_O[(size_t)M_TOK * D_MODELX];
__device__ float g_P[(size_t)BATCHX * NUM_HEADSX * SEQX * SEQX];  // 1 GiB

__device__ __forceinline__ unsigned pack_bf2(float x, float y) {
    __nv_bfloat162 t = __floats2bfloat162_rn(x, y);
    return *reinterpret_cast<unsigned*>(&t);
}

#define MMA_BF16(c, a0, a1, a2, a3, b0, b1)                                   \
    asm volatile(                                                             \
        "mma.sync.aligned.m16n8k16.row.col.f32.bf16.bf16.f32 "                \
        "{%0,%1,%2,%3},{%4,%5,%6,%7},{%8,%9},{%0,%1,%2,%3};"                  \
        : "+f"(c[0]), "+f"(c[1]), "+f"(c[2]), "+f"(c[3])                      \
        : "r"(a0), "r"(a1), "r"(a2), "r"(a3), "r"(b0), "r"(b1))

// ============================================================================
// NT bf16-split MMA GEMM: C = alpha * (A @ B^T) + bias
//   A: [M,K] row-major (lda), B: [N,K] row-major (ldb)
// MODE 0: plain + bias
// MODE 1: scores (z = b*16+h head offsets, C = P[z], alpha)
// MODE 2: AV (A = P[z], B = Vt[z], C = O head slice)
// MODE 3: V projection with transposed store into g_Vt layout
// Block tile 128x64x32, 256 threads (8 warps, 4x2), warp tile 32x32.
// ============================================================================
template <int MODE>
__global__ __launch_bounds__(256)
void mma_gemm(const float* __restrict__ A,
              const float* __restrict__ B,
              float* __restrict__ C,
              int lda, int ldb, int ldc,
              int K, float alpha,
              const float* __restrict__ bias)
{
    constexpr int BM = 128, BN = 64, BK = 32;
    constexpr int SA = 40;  // bf16 row stride (bank-conflict-free for frag loads)

    __shared__ __align__(16) __nv_bfloat16 AsH[BM * SA];
    __shared__ __align__(16) __nv_bfloat16 AsL[BM * SA];
    __shared__ __align__(16) __nv_bfloat16 BsH[BN * SA];
    __shared__ __align__(16) __nv_bfloat16 BsL[BN * SA];

    if (MODE == 1) {
        int z = blockIdx.z, b = z >> 4, h = z & 15;
        A += (size_t)b * SEQX * D_MODELX + h * D_HEADX;
        B += (size_t)b * SEQX * D_MODELX + h * D_HEADX;
        C += (size_t)z * SEQX * SEQX;
    } else if (MODE == 2) {
        int z = blockIdx.z, b = z >> 4, h = z & 15;
        A += (size_t)z * SEQX * SEQX;
        B += (size_t)z * D_HEADX * SEQX;
        C += (size_t)b * SEQX * D_MODELX + h * D_HEADX;
    }

    const int tid  = threadIdx.x;
    const int m0   = blockIdx.y * BM;
    const int n0   = blockIdx.x * BN;
    const int warp = tid >> 5, lane = tid & 31;
    const int wm = (warp & 3) * 32;   // warp M offset in tile
    const int wn = (warp >> 2) * 32;  // warp N offset in tile
    const int gr = lane >> 2;         // 0..7
    const int gc = lane & 3;          // 0..3

    float acc[2][4][4] = {};

    float4 ra[4], rb[2];

    // ---- prefetch tile 0 into registers ----
    {
        #pragma unroll
        for (int i = 0; i < 4; i++) {
            int idx = tid + i * 256, row = idx >> 3, c4 = idx & 7;
            ra[i] = *(const float4*)(A + (size_t)(m0 + row) * lda + c4 * 4);
        }
        #pragma unroll
        for (int i = 0; i < 2; i++) {
            int idx = tid + i * 256, row = idx >> 3, c4 = idx & 7;
            rb[i] = *(const float4*)(B + (size_t)(n0 + row) * ldb + c4 * 4);
        }
    }

    const int niter = K / BK;
    for (int it = 0; it < niter; ++it) {
        // ---- convert + store registers -> smem (hi/lo split) ----
        #pragma unroll
        for (int i = 0; i < 4; i++) {
            int idx = tid + i * 256, row = idx >> 3, c4 = idx & 7;
            float v0 = ra[i].x, v1 = ra[i].y, v2 = ra[i].z, v3 = ra[i].w;
            float h0 = __bfloat162float(__float2bfloat16_rn(v0));
            float h1 = __bfloat162float(__float2bfloat16_rn(v1));
            float h2 = __bfloat162float(__float2bfloat16_rn(v2));
            float h3 = __bfloat162float(__float2bfloat16_rn(v3));
            uint2 H, L;
            H.x = pack_bf2(v0, v1); H.y = pack_bf2(v2, v3);
            L.x = pack_bf2(v0 - h0, v1 - h1); L.y = pack_bf2(v2 - h2, v3 - h3);
            *(uint2*)&AsH[row * SA + c4 * 4] = H;
            *(uint2*)&AsL[row * SA + c4 * 4] = L;
        }
        #pragma unroll
        for (int i = 0; i < 2; i++) {
            int idx = tid + i * 256, row = idx >> 3, c4 = idx & 7;
            float v0 = rb[i].x, v1 = rb[i].y, v2 = rb[i].z, v3 = rb[i].w;
            float h0 = __bfloat162float(__float2bfloat16_rn(v0));
            float h1 = __bfloat162float(__float2bfloat16_rn(v1));
            float h2 = __bfloat162float(__float2bfloat16_rn(v2));
            float h3 = __bfloat162float(__float2bfloat16_rn(v3));
            uint2 H, L;
            H.x = pack_bf2(v0, v1); H.y = pack_bf2(v2, v3);
            L.x = pack_bf2(v0 - h0, v1 - h1); L.y = pack_bf2(v2 - h2, v3 - h3);
            *(uint2*)&BsH[row * SA + c4 * 4] = H;
            *(uint2*)&BsL[row * SA + c4 * 4] = L;
        }
        __syncthreads();

        // ---- prefetch next tile ----
        if (it + 1 < niter) {
            int k0 = (it + 1) * BK;
            #pragma unroll
            for (int i = 0; i < 4; i++) {
                int idx = tid + i * 256, row = idx >> 3, c4 = idx & 7;
                ra[i] = *(const float4*)(A + (size_t)(m0 + row) * lda + k0 + c4 * 4);
            }
            #pragma unroll
            for (int i = 0; i < 2; i++) {
                int idx = tid + i * 256, row = idx >> 3, c4 = idx & 7;
                rb[i] = *(const float4*)(B + (size_t)(n0 + row) * ldb + k0 + c4 * 4);
            }
        }

        // ---- compute: 2 k-steps of 16 ----
        #pragma unroll
        for (int ks = 0; ks < 2; ks++) {
            const int kb = ks * 16;
            unsigned aH[2][4], aL[2][4], bH[4][2], bL[4][2];
            #pragma unroll
            for (int mi = 0; mi < 2; mi++) {
                int r = (wm + mi * 16 + gr) * SA + kb + gc * 2;
                aH[mi][0] = *(const unsigned*)&AsH[r];
                aH[mi][1] = *(const unsigned*)&AsH[r + 8 * SA];
                aH[mi][2] = *(const unsigned*)&AsH[r + 8];
                aH[mi][3] = *(const unsigned*)&AsH[r + 8 * SA + 8];
                aL[mi][0] = *(const unsigned*)&AsL[r];
                aL[mi][1] = *(const unsigned*)&AsL[r + 8 * SA];
                aL[mi][2] = *(const unsigned*)&AsL[r + 8];
                aL[mi][3] = *(const unsigned*)&AsL[r + 8 * SA + 8];
            }
            #pragma unroll
            for (int ni = 0; ni < 4; ni++) {
                int r = (wn + ni * 8 + gr) * SA + kb + gc * 2;
                bH[ni][0] = *(const unsigned*)&BsH[r];
                bH[ni][1] = *(const unsigned*)&BsH[r + 8];
                bL[ni][0] = *(const unsigned*)&BsL[r];
                bL[ni][1] = *(const unsigned*)&BsL[r + 8];
            }
            #pragma unroll
            for (int mi = 0; mi < 2; mi++)
                #pragma unroll
                for (int ni = 0; ni < 4; ni++) {
                    MMA_BF16(acc[mi][ni], aH[mi][0], aH[mi][1], aH[mi][2], aH[mi][3],
                             bH[ni][0], bH[ni][1]);
                    MMA_BF16(acc[mi][ni], aH[mi][0], aH[mi][1], aH[mi][2], aH[mi][3],
                             bL[ni][0], bL[ni][1]);
                    MMA_BF16(acc[mi][ni], aL[mi][0], aL[mi][1], aL[mi][2], aL[mi][3],
                             bH[ni][0], bH[ni][1]);
                }
        }
        __syncthreads();
    }

    // ---- epilogue ----
    #pragma unroll
    for (int mi = 0; mi < 2; mi++)
        #pragma unroll
        for (int ni = 0; ni < 4; ni++) {
            int r = m0 + wm + mi * 16 + gr;
            int c = n0 + wn + ni * 8 + gc * 2;
            float* cc = acc[mi][ni];
            if (MODE == 3) {
                // transposed store into g_Vt [B*H][Dh][S]
                int b = r >> 11, s = r & 2047;
                int h = c >> 6, d = c & 63;
                float b0 = bias[c], b1 = bias[c + 1];
                size_t base = ((size_t)(b * 16 + h) * 64 + d) * 2048;
                C[base + s]            = cc[0] + b0;
                C[base + 2048 + s]     = cc[1] + b1;
                C[base + s + 8]        = cc[2] + b0;
                C[base + 2048 + s + 8] = cc[3] + b1;
            } else {
                float b0 = 0.f, b1 = 0.f;
                if (bias) { b0 = bias[c]; b1 = bias[c + 1]; }
                float2 v0 = make_float2(cc[0] * alpha + b0, cc[1] * alpha + b1);
                float2 v1 = make_float2(cc[2] * alpha + b0, cc[3] * alpha + b1);
                *(float2*)&C[(size_t)r * ldc + c]       = v0;
                *(float2*)&C[(size_t)(r + 8) * ldc + c] = v1;
            }
        }
}

// ============================================================================
// Fused softmax + head-average. One block per (b,q): processes 16 head rows,
// writes normalized P in place and avg[b,q,:].
// ============================================================================
__global__ __launch_bounds__(256)
void softmax_avg_kernel(float* __restrict__ P, float* __restrict__ avg)
{
    __shared__ float red[8];
    const int bq = blockIdx.x;           // b*2048 + q
    const int t  = threadIdx.x;
    const int b  = bq >> 11;
    const int q  = bq & 2047;

    float avgacc[8] = {};

    for (int h = 0; h < NUM_HEADSX; ++h) {
        float* p = P + ((size_t)(b * 16 + h) * SEQX + q) * SEQX;
        float v[8];
        float mx = -1e30f;
        #pragma unroll
        for (int i = 0; i < 8; i++) { v[i] = p[t + i * 256]; mx = fmaxf(mx, v[i]); }
        #pragma unroll
        for (int o = 16; o > 0; o >>= 1)
            mx = fmaxf(mx, __shfl_xor_sync(0xffffffffu, mx, o));
        if ((t & 31) == 0) red[t >> 5] = mx;
        __syncthreads();
        float bm = red[0];
        #pragma unroll
        for (int w = 1; w < 8; w++) bm = fmaxf(bm, red[w]);
        __syncthreads();

        float s = 0.f;
        #pragma unroll
        for (int i = 0; i < 8; i++) { v[i] = __expf(v[i] - bm); s += v[i]; }
        #pragma unroll
        for (int o = 16; o > 0; o >>= 1)
            s += __shfl_xor_sync(0xffffffffu, s, o);
        if ((t & 31) == 0) red[t >> 5] = s;
        __syncthreads();
        float bs = 0.f;
        #pragma unroll
        for (int w = 0; w < 8; w++) bs += red[w];
        float inv = 1.0f / bs;
        #pragma unroll
        for (int i = 0; i < 8; i++) {
            float pv = v[i] * inv;
            p[t + i * 256] = pv;
            avgacc[i] += pv;
        }
        __syncthreads();
    }

    float* a = avg + (size_t)bq * SEQX;
    #pragma unroll
    for (int i = 0; i < 8; i++)
        a[t + i * 256] = avgacc[i] * (1.0f / NUM_HEADSX);
}

// ============================================================================
// launch
// ============================================================================
extern "C" void kernel_launch(void* const* d_in, const int* in_sizes, int n_in,
                              void* d_out, int out_size)
{
    const float* x_q = (const float*)d_in[0];
    const float* x_k = (const float*)d_in[1];
    const float* x_v = (const float*)d_in[2];
    const float* Wq  = (const float*)d_in[3];
    const float* bq  = (const float*)d_in[4];
    const float* Wk  = (const float*)d_in[5];
    const float* bk  = (const float*)d_in[6];
    const float* Wv  = (const float*)d_in[7];
    const float* bv  = (const float*)d_in[8];
    const float* Wo  = (const float*)d_in[9];
    const float* bo  = (const float*)d_in[10];

    float* out = (float*)d_out;
    float* avg = out + (size_t)M_TOK * D_MODELX;

    float *gQ, *gK, *gVt, *gO, *gP;
    cudaGetSymbolAddress((void**)&gQ, g_Q);
    cudaGetSymbolAddress((void**)&gK, g_K);
    cudaGetSymbolAddress((void**)&gVt, g_Vt);
    cudaGetSymbolAddress((void**)&gO, g_O);
    cudaGetSymbolAddress((void**)&gP, g_P);

    dim3 blk(256);
    dim3 gproj(D_MODELX / 64, M_TOK / 128, 1);           // (16, 64)

    // 1-3) projections: [8192,1024] @ W^T + b  (V goes out transposed)
    mma_gemm<0><<<gproj, blk>>>(x_q, Wq, gQ, D_MODELX, D_MODELX, D_MODELX,
                                D_MODELX, 1.0f, bq);
    mma_gemm<0><<<gproj, blk>>>(x_k, Wk, gK, D_MODELX, D_MODELX, D_MODELX,
                                D_MODELX, 1.0f, bk);
    mma_gemm<3><<<gproj, blk>>>(x_v, Wv, gVt, D_MODELX, D_MODELX, 0,
                                D_MODELX, 1.0f, bv);

    // 4) scores: P[z] = (Q_h @ K_h^T) / 8
    dim3 gsc(SEQX / 64, SEQX / 128, BATCHX * NUM_HEADSX);  // (32, 16, 64)
    mma_gemm<1><<<gsc, blk>>>(gQ, gK, gP, D_MODELX, D_MODELX, SEQX,
                              D_HEADX, 0.125f, nullptr);

    // 5) fused softmax + head-average
    softmax_avg_kernel<<<M_TOK, blk>>>(gP, avg);

    // 6) AV: O_h = P[z] @ Vt[z]^T   (NT, N = 64)
    dim3 gav(1, SEQX / 128, BATCHX * NUM_HEADSX);          // (1, 16, 64)
    mma_gemm<2><<<gav, blk>>>(gP, gVt, gO, SEQX, SEQX, D_MODELX,
                              SEQX, 1.0f, nullptr);

    // 7) output projection
    mma_gemm<0><<<gproj, blk>>>(gO, Wo, out, D_MODELX, D_MODELX, D_MODELX,
                                D_MODELX, 1.0f, bo);
}